// round 1
// baseline (speedup 1.0000x reference)
#include <cuda_runtime.h>

#define EE 25
#define HH 37
#define NJ 6
#define CELLS (HH * EE)      // 925
#define TOT   (NJ * CELLS)   // 5550
#define GAMMA 0.9f
#define ADD 12

// packed (d+1) tables, 2 bits per j
// dr = {0,1,1,0,-1,-1} -> {1,2,2,1,0,0} ; dc = {1,0,-1,-1,0,1} -> {2,1,0,0,1,2}
#define DR_PACK 105u    // 1 | 2<<2 | 2<<4 | 1<<6 | 0<<8 | 0<<10
#define DC_PACK 2310u   // 2 | 1<<2 | 0<<4 | 0<<6 | 1<<8 | 2<<10

__global__ __launch_bounds__(256) void vin_kernel(
    const float* __restrict__ goals,   // [B,6,25,25]
    const int*   __restrict__ state,   // [B,3]
    const float* __restrict__ obst,    // [B,25,25]
    const int*   __restrict__ n_iter,  // [1]
    float* __restrict__ out)           // [B,4]
{
    __shared__ float    w  [NJ][HH][EE];
    __shared__ float    val[NJ][HH][EE];
    __shared__ unsigned gb [NJ][HH];   // goal bitmask per (j,row)
    __shared__ unsigned ob [HH];       // free-cell (om) bitmask per row

    const int b   = blockIdx.x;
    const int tid = threadIdx.x;

    // ---- build bitmasks: task t<37 -> ob row, else gb row ----
    for (int t = tid; t < HH * (NJ + 1); t += blockDim.x) {
        int r, j;
        if (t < HH) { r = t; j = -1; }
        else        { int tt = t - HH; j = tt / HH; r = tt - (tt / HH) * HH; }
        unsigned bits = 0u;
        #pragma unroll 1
        for (int c = 0; c < EE; ++c) {
            int u = r + (c >> 1) - ADD;          // inverse axial map
            if (u >= 0 && u < EE) {
                if (j < 0) {
                    if (obst[(b * EE + u) * EE + c] == 0.0f) bits |= (1u << c);
                } else {
                    if (goals[((b * NJ + j) * EE + u) * EE + c] != 0.0f) bits |= (1u << c);
                }
            }
        }
        if (j < 0) ob[r] = bits; else gb[j][r] = bits;
    }
    // ---- zero val ----
    for (int idx = tid; idx < TOT; idx += blockDim.x)
        ((float*)val)[idx] = 0.0f;
    __syncthreads();

    const int iters = n_iter[0];

    for (int s = 0; s < iters; ++s) {
        // phase A: w = om * (g + gamma * val)
        for (int idx = tid; idx < TOT; idx += blockDim.x) {
            int j   = idx / CELLS;
            int rem = idx - j * CELLS;
            int r   = rem / EE;
            int c   = rem - r * EE;
            float om = (float)((ob[r]    >> c) & 1u);
            float g  = (float)((gb[j][r] >> c) & 1u);
            ((float*)w)[idx] = om * (g + GAMMA * ((float*)val)[idx]);
        }
        __syncthreads();
        // phase B: val = om * max(4 action reads of w)
        for (int idx = tid; idx < TOT; idx += blockDim.x) {
            int j   = idx / CELLS;
            int rem = idx - j * CELLS;
            int r   = rem / EE;
            int c   = rem - r * EE;
            float v = 0.0f;
            if ((ob[r] >> c) & 1u) {
                int dr = (int)((DR_PACK >> (2 * j)) & 3u) - 1;
                int dc = (int)((DC_PACK >> (2 * j)) & 3u) - 1;
                int rp = r + dr, cp = c + dc;
                int rm = r - dr, cm = c - dc;
                float a0 = (rp >= 0 && rp < HH && cp >= 0 && cp < EE) ? w[j][rp][cp] : 0.0f;
                float a1 = (rm >= 0 && rm < HH && cm >= 0 && cm < EE) ? w[j][rm][cm] : 0.0f;
                int j1 = (j == 5) ? 0 : j + 1;
                int j5 = (j == 0) ? 5 : j - 1;
                float a2 = w[j1][r][c];
                float a3 = w[j5][r][c];
                v = fmaxf(fmaxf(a0, a1), fmaxf(a2, a3));
            }
            ((float*)val)[idx] = v;
        }
        __syncthreads();
    }

    // ---- final extraction: q[a] = om[uu,v] * w_final[PERM[a*6+rot]][uu+dr, v+dc] ----
    if (tid < 4) {
        int a     = tid;
        int alpha = state[b * 3 + 0];
        int u     = state[b * 3 + 1];
        int v     = state[b * 3 + 2];
        int rot   = (alpha + 1) % 6;
        int uu    = u - (v >> 1) + ADD;

        int p, ddr = 0, ddc = 0;
        if (a == 0) {
            p = rot;
            ddr =  ((int)((DR_PACK >> (2 * rot)) & 3u) - 1);
            ddc =  ((int)((DC_PACK >> (2 * rot)) & 3u) - 1);
        } else if (a == 1) {
            p = rot;
            ddr = -((int)((DR_PACK >> (2 * rot)) & 3u) - 1);
            ddc = -((int)((DC_PACK >> (2 * rot)) & 3u) - 1);
        } else if (a == 2) {
            p = (rot + 1) % 6;
        } else {
            p = (rot + 5) % 6;
        }

        float q = 0.0f;
        if ((ob[uu] >> v) & 1u) {
            int rp = uu + ddr, cp = v + ddc;
            if (rp >= 0 && rp < HH && cp >= 0 && cp < EE) {
                float om2 = (float)((ob[rp]    >> cp) & 1u);
                float g   = (float)((gb[p][rp] >> cp) & 1u);
                q = om2 * (g + GAMMA * val[p][rp][cp]);
            }
        }
        out[b * 4 + a] = q;
    }
}

extern "C" void kernel_launch(void* const* d_in, const int* in_sizes, int n_in,
                              void* d_out, int out_size) {
    const float* goals  = (const float*)d_in[0];
    const int*   state  = (const int*)  d_in[1];
    const float* obst   = (const float*)d_in[2];
    const int*   n_iter = (const int*)  d_in[3];
    float* out = (float*)d_out;

    int B = out_size / 4;   // 512
    vin_kernel<<<B, 256>>>(goals, state, obst, n_iter, out);
}

// round 3
// speedup vs baseline: 1.9386x; 1.9386x over previous
#include <cuda_runtime.h>

#define EE 25
#define HH 37
#define NJ 6
#define PE 27                 // padded cols (halo at 0 and 26)
#define PH 39                 // padded rows (halo at 0 and 38)
#define JSTR (PH * PE)        // 1053
#define NF   (NJ * JSTR)      // 6318 floats per buffer
#define ADD 12
#define GAMMA 0.9f
#define NTH 224
#define NROWS (NJ * HH)       // 222

// packed (d+1) tables, 2 bits per j
// dr = {0,1,1,0,-1,-1} ; dc = {1,0,-1,-1,0,1}
#define DR_PACK 105u
#define DC_PACK 2310u

#define SMEM_FLOATS (2 * NF + JSTR)                // sA, sB, OMG
#define SMEM_BYTES  ((SMEM_FLOATS + HH + NROWS) * 4)

__global__ __launch_bounds__(NTH, 4) void vin_kernel(
    const float* __restrict__ goals,   // [B,6,25,25]
    const int*   __restrict__ state,   // [B,3]
    const float* __restrict__ obst,    // [B,25,25]
    const int*   __restrict__ n_iter,  // [1]
    float* __restrict__ out)           // [B,4]
{
    extern __shared__ float sm[];
    float* sA  = sm;
    float* sB  = sm + NF;
    float* OMG = sm + 2 * NF;
    unsigned* obsh = (unsigned*)(sm + SMEM_FLOATS);   // [37]
    unsigned* cgsh = obsh + HH;                       // [222] = gb & ob

    const int b   = blockIdx.x;
    const int tid = threadIdx.x;

    // ---- zero the float region (buffers + OMG, incl. halos) ----
    for (int i = tid; i < SMEM_FLOATS; i += NTH) sm[i] = 0.0f;

    // ---- pass 1: build bitmasks (t<37 -> ob row, else raw goal row) ----
    for (int t = tid; t < HH * (NJ + 1); t += NTH) {
        int r, j;
        if (t < HH) { r = t; j = -1; }
        else        { int tt = t - HH; j = tt / HH; r = tt - j * HH; }
        unsigned bits = 0u;
        #pragma unroll 1
        for (int c = 0; c < EE; ++c) {
            int u = r + (c >> 1) - ADD;          // inverse axial map
            if (u >= 0 && u < EE) {
                if (j < 0) {
                    if (obst[(b * EE + u) * EE + c] == 0.0f) bits |= (1u << c);
                } else {
                    if (goals[((b * NJ + j) * EE + u) * EE + c] != 0.0f) bits |= (1u << c);
                }
            }
        }
        if (j < 0) obsh[r] = bits; else cgsh[t - HH] = bits;
    }
    __syncthreads();

    // ---- pass 2: OMG = gamma*om (interior), cg = gb & ob, seed sA = C ----
    for (int i = tid; i < HH * EE; i += NTH) {
        int r = i / EE, c = i - (i / EE) * EE;
        OMG[(r + 1) * PE + c + 1] = GAMMA * (float)((obsh[r] >> c) & 1u);
    }

    // per-thread row precompute
    int j = 0, r = 0, off_c = 0, off_0 = 0, off_1 = 0, off_2 = 0, off_3 = 0, omg_off = 0;
    unsigned cgme = 0u;
    const bool active = (tid < NROWS);
    if (active) {
        j = tid / HH;
        r = tid - j * HH;
        int dr = (int)((DR_PACK >> (2 * j)) & 3u) - 1;
        int dc = (int)((DC_PACK >> (2 * j)) & 3u) - 1;
        int j1 = (j == 5) ? 0 : j + 1;
        int j5 = (j == 0) ? 5 : j - 1;
        int rowp = (r + 1) * PE + 1;
        off_c  = j  * JSTR + rowp;
        off_0  = j  * JSTR + (r + 1 + dr) * PE + 1 + dc;
        off_1  = j  * JSTR + (r + 1 - dr) * PE + 1 - dc;
        off_2  = j1 * JSTR + rowp;
        off_3  = j5 * JSTR + rowp;
        omg_off = rowp;

        cgme = cgsh[tid] & obsh[r];
        cgsh[tid] = cgme;
        // seed: sA = C (sparse goal cells = 1.0)
        unsigned bits = cgme;
        while (bits) {
            int c = __ffs(bits) - 1;
            sA[off_c + c] = 1.0f;
            bits &= bits - 1;
        }
    }
    __syncthreads();

    const int iters = n_iter[0];
    float* src = sA;
    float* dst = sB;

    for (int s = 0; s < iters; ++s) {
        if (active) {
            const float* p0 = src + off_0;
            const float* p1 = src + off_1;
            const float* p2 = src + off_2;
            const float* p3 = src + off_3;
            const float* po = OMG + omg_off;
            float*       pd = dst + off_c;
            #pragma unroll
            for (int c = 0; c < EE; ++c) {
                float a0 = p0[c];
                float a1 = p1[c];
                float a2 = p2[c];
                float a3 = p3[c];
                float m  = fmaxf(fmaxf(a0, a1), fmaxf(a2, a3));
                pd[c] = po[c] * m;
            }
            // sparse goal add (exclusive row ownership -> no race)
            unsigned bits = cgme;
            while (bits) {
                int c = __ffs(bits) - 1;
                pd[c] += 1.0f;
                bits &= bits - 1;
            }
        }
        __syncthreads();
        float* t_ = src; src = dst; dst = t_;
    }
    // src now holds final s_plus = C + gamma*val_final  (halo = 0)

    // ---- extraction: q[a] = ob(uu,v) ? s_plus[p][n] : 0 ----
    if (tid < 4) {
        int a     = tid;
        int alpha = state[b * 3 + 0];
        int u     = state[b * 3 + 1];
        int v     = state[b * 3 + 2];
        int rot   = (alpha + 1) % 6;
        int uu    = u - (v >> 1) + ADD;

        int p, ddr = 0, ddc = 0;
        int drr = (int)((DR_PACK >> (2 * rot)) & 3u) - 1;
        int dcc = (int)((DC_PACK >> (2 * rot)) & 3u) - 1;
        if (a == 0)      { p = rot; ddr =  drr; ddc =  dcc; }
        else if (a == 1) { p = rot; ddr = -drr; ddc = -dcc; }
        else if (a == 2) { p = (rot + 1) % 6; }
        else             { p = (rot + 5) % 6; }

        float q = 0.0f;
        if ((obsh[uu] >> v) & 1u) {
            // padded indices always in range: uu+ddr in [-1,37] -> [0,38]
            q = src[p * JSTR + (uu + ddr + 1) * PE + (v + ddc + 1)];
        }
        out[b * 4 + a] = q;
    }
}

extern "C" void kernel_launch(void* const* d_in, const int* in_sizes, int n_in,
                              void* d_out, int out_size) {
    const float* goals  = (const float*)d_in[0];
    const int*   state  = (const int*)  d_in[1];
    const float* obst   = (const float*)d_in[2];
    const int*   n_iter = (const int*)  d_in[3];
    float* out = (float*)d_out;

    cudaFuncSetAttribute(vin_kernel,
                         cudaFuncAttributeMaxDynamicSharedMemorySize, SMEM_BYTES);

    int B = out_size / 4;   // 512
    vin_kernel<<<B, NTH, SMEM_BYTES>>>(goals, state, obst, n_iter, out);
}

// round 4
// speedup vs baseline: 2.7989x; 1.4438x over previous
#include <cuda_runtime.h>

#define EE 25
#define HH 37
#define NJ 6
#define PE 28                 // padded cols (even -> half-split conflict-free)
#define PH 39                 // padded rows
#define JSTR (PH * PE)        // 1092
#define NF   (NJ * JSTR)      // 6552 floats per buffer
#define ADDC 12
#define GAMMA 0.9f
#define NTH 448               // 14 warps: 2 threads per row
#define NROWS (NJ * HH)       // 222

// dr = {0,1,1,0,-1,-1} ; dc = {1,0,-1,-1,0,1}   packed as (d+1), 2 bits per j
#define DR_PACK 105u
#define DC_PACK 2310u

#define SMEM_FLOATS (2 * NF)
#define SMEM_BYTES  ((SMEM_FLOATS + HH + NROWS) * 4)

__global__ __launch_bounds__(NTH, 4) void vin_kernel(
    const float* __restrict__ goals,   // [B,6,25,25]
    const int*   __restrict__ state,   // [B,3]
    const float* __restrict__ obst,    // [B,25,25]
    const int*   __restrict__ n_iter,  // [1]
    float* __restrict__ out)           // [B,4]
{
    extern __shared__ float sm[];
    float* sA = sm;
    float* sB = sm + NF;
    unsigned* obsh = (unsigned*)(sm + SMEM_FLOATS);   // [37]  free-cell bits
    unsigned* gbsh = obsh + HH;                       // [222] raw goal bits

    const int b   = blockIdx.x;
    const int tid = threadIdx.x;

    // ---- zero both buffers (incl. halos) ----
    for (int i = tid; i < SMEM_FLOATS; i += NTH) sm[i] = 0.0f;

    // ---- build bitmasks: task t<37 -> ob row, else raw goal row ----
    for (int t = tid; t < HH * (NJ + 1); t += NTH) {
        int r, j;
        if (t < HH) { r = t; j = -1; }
        else        { int tt = t - HH; j = tt / HH; r = tt - j * HH; }
        unsigned bits = 0u;
        #pragma unroll 1
        for (int c = 0; c < EE; ++c) {
            int u = r + (c >> 1) - ADDC;          // inverse axial map
            if (u >= 0 && u < EE) {
                if (j < 0) {
                    if (obst[(b * EE + u) * EE + c] == 0.0f) bits |= (1u << c);
                } else {
                    if (goals[((b * NJ + j) * EE + u) * EE + c] != 0.0f) bits |= (1u << c);
                }
            }
        }
        if (j < 0) obsh[r] = bits; else gbsh[t - HH] = bits;
    }
    __syncthreads();

    // ---- per-thread (row, half) setup ----
    const int warp = tid >> 5;
    const int lane = tid & 31;
    const int half = lane >> 4;          // 0: cols 0..12, 1: cols 13..25(halo)
    const int row  = warp * 16 + (lane & 15);
    const bool active = (row < NROWS);

    int off_c = 0, off_0 = 0, off_1 = 0, off_2 = 0, off_3 = 0;
    unsigned maskO = 0u, maskG = 0u;

    if (active) {
        int j = row / HH;
        int r = row - j * HH;
        int dr = (int)((DR_PACK >> (2 * j)) & 3u) - 1;
        int dc = (int)((DC_PACK >> (2 * j)) & 3u) - 1;
        int j1 = (j == 5) ? 0 : j + 1;
        int j5 = (j == 0) ? 5 : j - 1;
        int hoff = half * 13;
        int colbase = 1 + hoff;
        off_c = j  * JSTR + (r + 1) * PE + colbase;
        off_0 = j  * JSTR + (r + 1 + dr) * PE + colbase + dc;
        off_1 = j  * JSTR + (r + 1 - dr) * PE + colbase - dc;
        off_2 = j1 * JSTR + (r + 1) * PE + colbase;
        off_3 = j5 * JSTR + (r + 1) * PE + colbase;

        unsigned ob = obsh[r];
        unsigned cg = gbsh[row] & ob;
        maskO = (ob >> hoff) & 0x1FFFu;   // local 13 bits (bit12 of half1 == 0)
        maskG = (cg >> hoff) & 0x1FFFu;

        // seed sA = C (sparse goal cells = 1.0)
        unsigned bits = maskG;
        while (bits) {
            int c = __ffs(bits) - 1;
            sA[off_c + c] = 1.0f;
            bits &= bits - 1;
        }
    }
    __syncthreads();

    const int iters = n_iter[0];
    float* src = sA;
    float* dst = sB;

    for (int s = 0; s < iters; ++s) {
        if (active) {
            const float* p0 = src + off_0;
            const float* p1 = src + off_1;
            const float* p2 = src + off_2;
            const float* p3 = src + off_3;
            float*       pd = dst + off_c;
            #pragma unroll
            for (int c = 0; c < 13; ++c) {
                float m = fmaxf(fmaxf(p0[c], p1[c]), fmaxf(p2[c], p3[c]));
                float omg = (maskO & (1u << c)) ? GAMMA : 0.0f;
                pd[c] = omg * m;
            }
            // sparse goal add (same thread owns these cells -> no race)
            unsigned bits = maskG;
            while (bits) {
                int c = __ffs(bits) - 1;
                pd[c] += 1.0f;
                bits &= bits - 1;
            }
        }
        __syncthreads();
        float* t_ = src; src = dst; dst = t_;
    }
    // src holds final s_plus = C + gamma*om*max(...)  (halo = 0)

    // ---- extraction: q[a] = ob(uu,v) ? s_plus[p][neighbor] : 0 ----
    if (tid < 4) {
        int a     = tid;
        int alpha = state[b * 3 + 0];
        int u     = state[b * 3 + 1];
        int v     = state[b * 3 + 2];
        int rot   = (alpha + 1) % 6;
        int uu    = u - (v >> 1) + ADDC;

        int p, ddr = 0, ddc = 0;
        int drr = (int)((DR_PACK >> (2 * rot)) & 3u) - 1;
        int dcc = (int)((DC_PACK >> (2 * rot)) & 3u) - 1;
        if (a == 0)      { p = rot; ddr =  drr; ddc =  dcc; }
        else if (a == 1) { p = rot; ddr = -drr; ddc = -dcc; }
        else if (a == 2) { p = (rot + 1) % 6; }
        else             { p = (rot + 5) % 6; }

        float q = 0.0f;
        if ((obsh[uu] >> v) & 1u) {
            q = src[p * JSTR + (uu + ddr + 1) * PE + (v + ddc + 1)];
        }
        out[b * 4 + a] = q;
    }
}

extern "C" void kernel_launch(void* const* d_in, const int* in_sizes, int n_in,
                              void* d_out, int out_size) {
    const float* goals  = (const float*)d_in[0];
    const int*   state  = (const int*)  d_in[1];
    const float* obst   = (const float*)d_in[2];
    const int*   n_iter = (const int*)  d_in[3];
    float* out = (float*)d_out;

    cudaFuncSetAttribute(vin_kernel,
                         cudaFuncAttributeMaxDynamicSharedMemorySize, SMEM_BYTES);

    int B = out_size / 4;   // 512
    vin_kernel<<<B, NTH, SMEM_BYTES>>>(goals, state, obst, n_iter, out);
}

// round 5
// speedup vs baseline: 4.1918x; 1.4977x over previous
#include <cuda_runtime.h>

#define EE 25
#define HH 37
#define NJ 6
#define PEC 27                  // padded cell columns
#define PHR 39                  // padded cell rows
#define CSTR 6                  // floats per cell (slots [j0,j3,j1,j4,j2,j5])
#define ROWF (PEC * CSTR)       // 162 floats per padded row
#define NF   (PHR * ROWF)       // 6318 floats per buffer
#define ADDC 12
#define GAMMA 0.9f
#define NTH 448
#define NCELLS (HH * EE)        // 925

// dr = {0,1,1,0,-1,-1} ; dc = {1,0,-1,-1,0,1}  packed as (d+1), 2 bits per k
#define DR_PACK 105u
#define DC_PACK 2310u

#define SMEM_FLOATS (2 * NF)
#define SMEM_BYTES  ((SMEM_FLOATS + HH + NJ * HH) * 4)

// neighbor pair-load float offsets: D_k + 2*(k%3)
//  k: (dr,dc) -> 6*(dr*27+dc) : 0:+6  1:+162  2:+156  3:-6  4:-162  5:-156

__device__ __forceinline__ void cell_update(
    const float* __restrict__ sb, float* __restrict__ db,
    float A, unsigned cg)
{
    float2 o0 = *(const float2*)(sb + 0);     // (w0, w3)
    float2 o1 = *(const float2*)(sb + 2);     // (w1, w4)
    float2 o2 = *(const float2*)(sb + 4);     // (w2, w5)
    float2 n0 = *(const float2*)(sb + 6);     // dir0: (slot0, slot3)
    float2 n1 = *(const float2*)(sb + 164);   // dir1: (slot1, slot4)
    float2 n2 = *(const float2*)(sb + 160);   // dir2: (slot2, slot5)
    float2 n3 = *(const float2*)(sb - 6);     // dir3: (slot0, slot3)
    float2 n4 = *(const float2*)(sb - 160);   // dir4: (slot1, slot4)
    float2 n5 = *(const float2*)(sb - 152);   // dir5: (slot2, slot5)

    // j<3: a0=n_j.x  a1=n_{j+3}.x ; j>=3: a0=n_j.y  a1=n_{j-3}.y
    // a2=own[(j+1)%6], a3=own[(j+5)%6]
    float m0 = fmaxf(fmaxf(n0.x, n3.x), fmaxf(o1.x, o2.y));
    float m1 = fmaxf(fmaxf(n1.x, n4.x), fmaxf(o2.x, o0.x));
    float m2 = fmaxf(fmaxf(n2.x, n5.x), fmaxf(o0.y, o1.x));
    float m3 = fmaxf(fmaxf(n3.y, n0.y), fmaxf(o1.y, o2.x));
    float m4 = fmaxf(fmaxf(n4.y, n1.y), fmaxf(o2.y, o0.y));
    float m5 = fmaxf(fmaxf(n5.y, n2.y), fmaxf(o0.x, o1.y));

    float B0 = (cg &  1u) ? 1.0f : 0.0f;
    float B1 = (cg &  2u) ? 1.0f : 0.0f;
    float B2 = (cg &  4u) ? 1.0f : 0.0f;
    float B3 = (cg &  8u) ? 1.0f : 0.0f;
    float B4 = (cg & 16u) ? 1.0f : 0.0f;
    float B5 = (cg & 32u) ? 1.0f : 0.0f;

    float2 r0, r1, r2;
    r0.x = fmaf(A, m0, B0);  r0.y = fmaf(A, m3, B3);
    r1.x = fmaf(A, m1, B1);  r1.y = fmaf(A, m4, B4);
    r2.x = fmaf(A, m2, B2);  r2.y = fmaf(A, m5, B5);
    *(float2*)(db + 0) = r0;
    *(float2*)(db + 2) = r1;
    *(float2*)(db + 4) = r2;
}

__global__ __launch_bounds__(NTH, 4) void vin_kernel(
    const float* __restrict__ goals,   // [B,6,25,25]
    const int*   __restrict__ state,   // [B,3]
    const float* __restrict__ obst,    // [B,25,25]
    const int*   __restrict__ n_iter,  // [1]
    float* __restrict__ out)           // [B,4]
{
    extern __shared__ float sm[];
    float* sA = sm;
    float* sB = sm + NF;
    unsigned* obsh = (unsigned*)(sm + SMEM_FLOATS);   // [37]  free-cell bits
    unsigned* gbsh = obsh + HH;                       // [6*37] raw goal bits

    const int b   = blockIdx.x;
    const int tid = threadIdx.x;

    // ---- zero both buffers (incl. halos) ----
    for (int i = tid; i < SMEM_FLOATS; i += NTH) sm[i] = 0.0f;

    // ---- build bitmasks (t<37 -> obstacle row, else goal row per j) ----
    for (int t = tid; t < HH * (NJ + 1); t += NTH) {
        int r, j;
        if (t < HH) { r = t; j = -1; }
        else        { int tt = t - HH; j = tt / HH; r = tt - j * HH; }
        unsigned bits = 0u;
        #pragma unroll 1
        for (int c = 0; c < EE; ++c) {
            int u = r + (c >> 1) - ADDC;          // inverse axial map
            if (u >= 0 && u < EE) {
                if (j < 0) {
                    if (obst[(b * EE + u) * EE + c] == 0.0f) bits |= (1u << c);
                } else {
                    if (goals[((b * NJ + j) * EE + u) * EE + c] != 0.0f) bits |= (1u << c);
                }
            }
        }
        if (j < 0) obsh[r] = bits; else gbsh[t - HH] = bits;
    }
    __syncthreads();

    // ---- per-thread cell setup (cells tid, tid+448, tid+896 if tid<29) ----
    int      cb[3];
    float    Am[3];
    unsigned cg[3];
    const int ncell = (tid < NCELLS - 2 * NTH) ? 3 : 2;   // tid<29 -> 3

    #pragma unroll
    for (int q = 0; q < 3; ++q) {
        int i = tid + q * NTH;
        cb[q] = 0; Am[q] = 0.0f; cg[q] = 0u;
        if (i < NCELLS) {
            int r = i / EE;
            int c = i - r * EE;
            cb[q] = (r + 1) * ROWF + (c + 1) * CSTR;
            unsigned ob = (obsh[r] >> c) & 1u;
            Am[q] = ob ? GAMMA : 0.0f;
            unsigned g = 0u;
            #pragma unroll
            for (int j = 0; j < NJ; ++j)
                g |= ((gbsh[j * HH + r] >> c) & 1u) << j;
            cg[q] = ob ? g : 0u;
            // seed sA = C : slot pos(j) = 2*(j%3) + j/3
            unsigned bits = cg[q];
            while (bits) {
                int j = __ffs(bits) - 1;
                sA[cb[q] + 2 * (j % 3) + (j / 3)] = 1.0f;
                bits &= bits - 1;
            }
        }
    }
    __syncthreads();

    const int iters = n_iter[0];
    float* sp = sA;
    float* dp = sB;

    for (int s = 0; s < iters; ++s) {
        cell_update(sp + cb[0], dp + cb[0], Am[0], cg[0]);
        cell_update(sp + cb[1], dp + cb[1], Am[1], cg[1]);
        if (ncell == 3)
            cell_update(sp + cb[2], dp + cb[2], Am[2], cg[2]);
        __syncthreads();
        float* t_ = sp; sp = dp; dp = t_;
    }
    // sp holds final s_plus = C + gamma*om*max(...)  (halo = 0)

    // ---- extraction: q[a] = ob(uu,v) ? s_plus[p][neighbor] : 0 ----
    if (tid < 4) {
        int a     = tid;
        int alpha = state[b * 3 + 0];
        int u     = state[b * 3 + 1];
        int v     = state[b * 3 + 2];
        int rot   = (alpha + 1) % 6;
        int uu    = u - (v >> 1) + ADDC;

        int p, ddr = 0, ddc = 0;
        int drr = (int)((DR_PACK >> (2 * rot)) & 3u) - 1;
        int dcc = (int)((DC_PACK >> (2 * rot)) & 3u) - 1;
        if (a == 0)      { p = rot; ddr =  drr; ddc =  dcc; }
        else if (a == 1) { p = rot; ddr = -drr; ddc = -dcc; }
        else if (a == 2) { p = (rot + 1) % 6; }
        else             { p = (rot + 5) % 6; }

        float q = 0.0f;
        if ((obsh[uu] >> v) & 1u) {
            q = sp[(uu + ddr + 1) * ROWF + (v + ddc + 1) * CSTR
                   + 2 * (p % 3) + (p / 3)];
        }
        out[b * 4 + a] = q;
    }
}

extern "C" void kernel_launch(void* const* d_in, const int* in_sizes, int n_in,
                              void* d_out, int out_size) {
    const float* goals  = (const float*)d_in[0];
    const int*   state  = (const int*)  d_in[1];
    const float* obst   = (const float*)d_in[2];
    const int*   n_iter = (const int*)  d_in[3];
    float* out = (float*)d_out;

    cudaFuncSetAttribute(vin_kernel,
                         cudaFuncAttributeMaxDynamicSharedMemorySize, SMEM_BYTES);

    int B = out_size / 4;   // 512
    vin_kernel<<<B, NTH, SMEM_BYTES>>>(goals, state, obst, n_iter, out);
}

// round 6
// speedup vs baseline: 5.1744x; 1.2344x over previous
#include <cuda_runtime.h>

#define EE 25
#define HH 37
#define NJ 6
#define CSTR 6                  // floats per cell, slots [w0,w3,w1,w4,w2,w5]
#define PEC 27                  // padded cols
#define ROWF (PEC * CSTR)       // 162 floats per padded row
#define PHR 40                  // padded rows + guard row (all-zero reads)
#define NF (PHR * ROWF)         // 6480 floats per buffer
#define NTH 480
#define NBAND 19
#define NVP (NBAND * EE)        // 475 vertical pairs
#define GAMMA 0.9f
#define ADDC 12

// dr = {0,1,1,0,-1,-1} ; dc = {1,0,-1,-1,0,1}  packed (d+1), 2 bits per k
#define DR_PACK 105u
#define DC_PACK 2310u

#define SMEM_WORDS (2 * NF + HH + NJ * HH)
#define SMEM_BYTES (SMEM_WORDS * 4)

__device__ __forceinline__ float2 ld2(const float* p) { return *(const float2*)p; }

__global__ __launch_bounds__(NTH, 4) void vin_kernel(
    const float* __restrict__ goals,   // [B,6,25,25]
    const int*   __restrict__ state,   // [B,3]
    const float* __restrict__ obst,    // [B,25,25]
    const int*   __restrict__ n_iter,  // [1]
    float* __restrict__ out)           // [B,4]
{
    extern __shared__ float sm[];
    unsigned* obsh = (unsigned*)(sm + 2 * NF);   // [37]
    unsigned* gbsh = obsh + HH;                  // [6*37]

    const int b   = blockIdx.x;
    const int tid = threadIdx.x;

    // zero both buffers (incl. halos & guard rows)
    for (int i = tid; i < 2 * NF; i += NTH) sm[i] = 0.0f;

    // build bitmasks (t<37 -> obstacle row, else goal row per j)
    for (int t = tid; t < HH * (NJ + 1); t += NTH) {
        int r, j;
        if (t < HH) { r = t; j = -1; }
        else        { int tt = t - HH; j = tt / HH; r = tt - j * HH; }
        unsigned bits = 0u;
        #pragma unroll 1
        for (int c = 0; c < EE; ++c) {
            int u = r + (c >> 1) - ADDC;
            if (u >= 0 && u < EE) {
                if (j < 0) {
                    if (obst[(b * EE + u) * EE + c] == 0.0f) bits |= (1u << c);
                } else {
                    if (goals[((b * NJ + j) * EE + u) * EE + c] != 0.0f) bits |= (1u << c);
                }
            }
        }
        if (j < 0) obsh[r] = bits; else gbsh[t - HH] = bits;
    }
    __syncthreads();

    const bool active = (tid < NVP);
    int baseA = 0;
    float AmA = 0.0f, AmB = 0.0f;
    unsigned cgA = 0u, cgB = 0u;
    float2 oA0 = {0,0}, oA1 = {0,0}, oA2 = {0,0};
    float2 oB0 = {0,0}, oB1 = {0,0}, oB2 = {0,0};

    if (active) {
        int band = tid / EE;
        int c    = tid - band * EE;
        int rA   = 2 * band;
        int rB   = rA + 1;
        baseA = (rA + 1) * ROWF + (c + 1) * CSTR;
        unsigned obA = (obsh[rA] >> c) & 1u;
        int rBc = (rB < HH) ? rB : (HH - 1);
        unsigned obB = (rB < HH) ? ((obsh[rB] >> c) & 1u) : 0u;
        AmA = obA ? GAMMA : 0.0f;
        AmB = obB ? GAMMA : 0.0f;
        unsigned gA = 0u, gB = 0u;
        #pragma unroll
        for (int j = 0; j < NJ; ++j) {
            gA |= ((gbsh[j * HH + rA ] >> c) & 1u) << j;
            gB |= ((gbsh[j * HH + rBc] >> c) & 1u) << j;
        }
        cgA = obA ? gA : 0u;
        cgB = obB ? gB : 0u;

        oA0 = make_float2((cgA &  1u) ? 1.f : 0.f, (cgA &  8u) ? 1.f : 0.f);
        oA1 = make_float2((cgA &  2u) ? 1.f : 0.f, (cgA & 16u) ? 1.f : 0.f);
        oA2 = make_float2((cgA &  4u) ? 1.f : 0.f, (cgA & 32u) ? 1.f : 0.f);
        oB0 = make_float2((cgB &  1u) ? 1.f : 0.f, (cgB &  8u) ? 1.f : 0.f);
        oB1 = make_float2((cgB &  2u) ? 1.f : 0.f, (cgB & 16u) ? 1.f : 0.f);
        oB2 = make_float2((cgB &  4u) ? 1.f : 0.f, (cgB & 32u) ? 1.f : 0.f);

        // seed sA = C
        *(float2*)(sm + baseA + 0) = oA0;
        *(float2*)(sm + baseA + 2) = oA1;
        *(float2*)(sm + baseA + 4) = oA2;
        *(float2*)(sm + baseA + ROWF + 0) = oB0;
        *(float2*)(sm + baseA + ROWF + 2) = oB1;
        *(float2*)(sm + baseA + ROWF + 4) = oB2;
    }
    __syncthreads();

    const int iters = n_iter[0];
    int spO = 0;

    for (int s = 0; s < iters; ++s) {
        if (active) {
            const float* S  = sm + spO + baseA;
            float*       D  = sm + (spO ^ NF) + baseA;
            const float* SB = S + ROWF;
            // A neighbor loads (dirs 0,2,3,4,5; dir1 = oB1 register)
            float2 a0 = ld2(S + 6);
            float2 a2 = ld2(S + 160);
            float2 a3 = ld2(S - 6);
            float2 a4 = ld2(S - 160);
            float2 a5 = ld2(S - 152);
            // B neighbor loads (dirs 0,1,2,3,5; dir4 = oA1 register)
            float2 b0 = ld2(SB + 6);
            float2 b1 = ld2(SB + 164);
            float2 b2 = ld2(SB + 160);
            float2 b3 = ld2(SB - 6);
            float2 b5 = ld2(SB - 152);

            float mA0 = fmaxf(fmaxf(a0.x, a3.x),  fmaxf(oA1.x, oA2.y));
            float mA1 = fmaxf(fmaxf(oB1.x, a4.x), fmaxf(oA2.x, oA0.x));
            float mA2 = fmaxf(fmaxf(a2.x, a5.x),  fmaxf(oA0.y, oA1.x));
            float mA3 = fmaxf(fmaxf(a3.y, a0.y),  fmaxf(oA1.y, oA2.x));
            float mA4 = fmaxf(fmaxf(a4.y, oB1.y), fmaxf(oA2.y, oA0.y));
            float mA5 = fmaxf(fmaxf(a5.y, a2.y),  fmaxf(oA0.x, oA1.y));

            float mB0 = fmaxf(fmaxf(b0.x, b3.x),  fmaxf(oB1.x, oB2.y));
            float mB1 = fmaxf(fmaxf(b1.x, oA1.x), fmaxf(oB2.x, oB0.x));
            float mB2 = fmaxf(fmaxf(b2.x, b5.x),  fmaxf(oB0.y, oB1.x));
            float mB3 = fmaxf(fmaxf(b3.y, b0.y),  fmaxf(oB1.y, oB2.x));
            float mB4 = fmaxf(fmaxf(oA1.y, b1.y), fmaxf(oB2.y, oB0.y));
            float mB5 = fmaxf(fmaxf(b5.y, b2.y),  fmaxf(oB0.x, oB1.y));

            oA0.x = fmaf(AmA, mA0, (cgA &  1u) ? 1.f : 0.f);
            oA0.y = fmaf(AmA, mA3, (cgA &  8u) ? 1.f : 0.f);
            oA1.x = fmaf(AmA, mA1, (cgA &  2u) ? 1.f : 0.f);
            oA1.y = fmaf(AmA, mA4, (cgA & 16u) ? 1.f : 0.f);
            oA2.x = fmaf(AmA, mA2, (cgA &  4u) ? 1.f : 0.f);
            oA2.y = fmaf(AmA, mA5, (cgA & 32u) ? 1.f : 0.f);
            oB0.x = fmaf(AmB, mB0, (cgB &  1u) ? 1.f : 0.f);
            oB0.y = fmaf(AmB, mB3, (cgB &  8u) ? 1.f : 0.f);
            oB1.x = fmaf(AmB, mB1, (cgB &  2u) ? 1.f : 0.f);
            oB1.y = fmaf(AmB, mB4, (cgB & 16u) ? 1.f : 0.f);
            oB2.x = fmaf(AmB, mB2, (cgB &  4u) ? 1.f : 0.f);
            oB2.y = fmaf(AmB, mB5, (cgB & 32u) ? 1.f : 0.f);

            float* DB = D + ROWF;
            *(float2*)(D  + 0) = oA0;
            *(float2*)(D  + 2) = oA1;
            *(float2*)(D  + 4) = oA2;
            *(float2*)(DB + 0) = oB0;
            *(float2*)(DB + 2) = oB1;
            *(float2*)(DB + 4) = oB2;
        }
        spO ^= NF;
        __syncthreads();
    }
    // sm + spO holds final s_plus = C + gamma*om*max(...)

    if (tid < 4) {
        int a     = tid;
        int alpha = state[b * 3 + 0];
        int u     = state[b * 3 + 1];
        int v     = state[b * 3 + 2];
        int rot   = (alpha + 1) % 6;
        int uu    = u - (v >> 1) + ADDC;

        int p, ddr = 0, ddc = 0;
        int drr = (int)((DR_PACK >> (2 * rot)) & 3u) - 1;
        int dcc = (int)((DC_PACK >> (2 * rot)) & 3u) - 1;
        if (a == 0)      { p = rot; ddr =  drr; ddc =  dcc; }
        else if (a == 1) { p = rot; ddr = -drr; ddc = -dcc; }
        else if (a == 2) { p = (rot + 1) % 6; }
        else             { p = (rot + 5) % 6; }

        float q = 0.0f;
        if ((obsh[uu] >> v) & 1u) {
            q = sm[spO + (uu + ddr + 1) * ROWF + (v + ddc + 1) * CSTR
                   + 2 * (p % 3) + (p / 3)];
        }
        out[b * 4 + a] = q;
    }
}

extern "C" void kernel_launch(void* const* d_in, const int* in_sizes, int n_in,
                              void* d_out, int out_size) {
    const float* goals  = (const float*)d_in[0];
    const int*   state  = (const int*)  d_in[1];
    const float* obst   = (const float*)d_in[2];
    const int*   n_iter = (const int*)  d_in[3];
    float* out = (float*)d_out;

    cudaFuncSetAttribute(vin_kernel,
                         cudaFuncAttributeMaxDynamicSharedMemorySize, SMEM_BYTES);

    int B = out_size / 4;   // 512
    vin_kernel<<<B, NTH, SMEM_BYTES>>>(goals, state, obst, n_iter, out);
}